// round 4
// baseline (speedup 1.0000x reference)
#include <cuda_runtime.h>

#define NN 50000
#define DD 128
#define EE 800000
#define EPSL 1e-5f

#define SCH 512
#define SNB ((NN + SCH - 1) / SCH)   // 98

// ---------------- scratch (device globals; no allocation allowed) -------------
__device__ float g_dinv[NN];
__device__ float g_tmp[NN * DD];   // dinv[i] * (ReLU(LN(h_i)) @ W)
__device__ float g_x1[NN * DD];    // x after layer0 + residual
__device__ float g_h2[NN * DD];    // layer1 output
__device__ int   g_cnt[NN];
__device__ int   g_start[NN];
__device__ int   g_cursor[NN];
__device__ int   g_esrc[EE];       // edge srcs bucketed by dst (CSR)
__device__ int   g_csum[SNB];

// ---------------- CSR build ----------------------------------------------------
__global__ void k_zero() {
    int i = blockIdx.x * blockDim.x + threadIdx.x;
    if (i < NN) g_cnt[i] = 0;
}

__global__ void k_hist(const int* __restrict__ dst) {
    int e = blockIdx.x * blockDim.x + threadIdx.x;
    if (e < EE) atomicAdd(&g_cnt[dst[e]], 1);
}

// per-chunk sums
__global__ void __launch_bounds__(SCH) k_scan_a() {
    __shared__ int sm[SCH];
    int t = threadIdx.x;
    int i = blockIdx.x * SCH + t;
    sm[t] = (i < NN) ? g_cnt[i] : 0;
    __syncthreads();
    for (int off = SCH / 2; off > 0; off >>= 1) {
        if (t < off) sm[t] += sm[t + off];
        __syncthreads();
    }
    if (t == 0) g_csum[blockIdx.x] = sm[0];
}

// in-chunk exclusive scan + self-computed chunk offset -> start/cursor (+dinv)
__global__ void __launch_bounds__(SCH) k_scan_c() {
    __shared__ int sm[SCH];
    __shared__ int base;
    int t = threadIdx.x;
    int i = blockIdx.x * SCH + t;
    int v = (i < NN) ? g_cnt[i] : 0;
    sm[t] = v;
    if (t == 0) {
        int run = 0;
        for (int j = 0; j < blockIdx.x; j++) run += g_csum[j];
        base = run;
    }
    __syncthreads();
    for (int off = 1; off < SCH; off <<= 1) {
        int x = (t >= off) ? sm[t - off] : 0;
        __syncthreads();
        sm[t] += x;
        __syncthreads();
    }
    if (i < NN) {
        int excl = sm[t] - v + base;
        g_start[i] = excl;
        g_cursor[i] = excl;
        g_dinv[i] = rsqrtf(1.0f + (float)v);
    }
}

__global__ void k_bucket(const int* __restrict__ src, const int* __restrict__ dst) {
    int e = blockIdx.x * blockDim.x + threadIdx.x;
    if (e < EE) {
        int pos = atomicAdd(&g_cursor[dst[e]], 1);
        g_esrc[pos] = src[e];
    }
}

// ---------------- fused LN + ReLU + GEMM + dinv prescale ----------------------
// g_tmp[i] = dinv[i] * ( ReLU( (h_i - mu)*rstd*g + bt ) @ W )
// Block 256 threads, tile 64 rows x 128 cols, k-tile 32. 48KB static smem.
#define TR 64
#define KT 32
__global__ void __launch_bounds__(256) k_ln_gemm(const float* __restrict__ h,
                          const float* __restrict__ g,
                          const float* __restrict__ bt,
                          const float* __restrict__ W) {
    __shared__ float As[TR * DD];    // 32KB
    __shared__ float Ws[KT * DD];    // 16KB

    int tid = threadIdx.x;
    int lane = tid & 31;
    int w = tid >> 5;
    int row0 = blockIdx.x * TR;

    // LayerNorm + ReLU into As: warp w handles rows w, w+8, ..., w+56
    for (int r = w; r < TR; r += 8) {
        int row = row0 + r;
        float4 v = make_float4(0.f, 0.f, 0.f, 0.f);
        if (row < NN) v = ((const float4*)(h + (size_t)row * DD))[lane];
        float s = v.x + v.y + v.z + v.w;
        #pragma unroll
        for (int o = 16; o; o >>= 1) s += __shfl_xor_sync(0xffffffffu, s, o);
        float mu = s * (1.0f / DD);
        float dx = v.x - mu, dy = v.y - mu, dz = v.z - mu, dw = v.w - mu;
        float q = dx * dx + dy * dy + dz * dz + dw * dw;
        #pragma unroll
        for (int o = 16; o; o >>= 1) q += __shfl_xor_sync(0xffffffffu, q, o);
        float rstd = rsqrtf(q * (1.0f / DD) + EPSL);
        float4 gg = ((const float4*)g)[lane];
        float4 bb = ((const float4*)bt)[lane];
        float4 o4;
        o4.x = fmaxf(fmaf(dx * rstd, gg.x, bb.x), 0.f);
        o4.y = fmaxf(fmaf(dy * rstd, gg.y, bb.y), 0.f);
        o4.z = fmaxf(fmaf(dz * rstd, gg.z, bb.z), 0.f);
        o4.w = fmaxf(fmaf(dw * rstd, gg.w, bb.w), 0.f);
        ((float4*)(As + r * DD))[lane] = o4;
    }

    // GEMM: warp w -> rows 8w..8w+7 ; lane -> cols 4*lane..4*lane+3
    float4 acc[8];
    #pragma unroll
    for (int i = 0; i < 8; i++) acc[i] = make_float4(0.f, 0.f, 0.f, 0.f);

    const float* aw = As + w * 8 * DD;

    for (int k0 = 0; k0 < DD; k0 += KT) {
        __syncthreads();
        {
            const float4* W4 = (const float4*)(W + (size_t)k0 * DD);
            float4* Ws4 = (float4*)Ws;
            #pragma unroll
            for (int i = tid; i < KT * DD / 4; i += 256) Ws4[i] = W4[i];
        }
        __syncthreads();

        #pragma unroll
        for (int kk = 0; kk < KT; kk += 4) {
            float4 wv0 = ((const float4*)(Ws + (kk + 0) * DD))[lane];
            float4 wv1 = ((const float4*)(Ws + (kk + 1) * DD))[lane];
            float4 wv2 = ((const float4*)(Ws + (kk + 2) * DD))[lane];
            float4 wv3 = ((const float4*)(Ws + (kk + 3) * DD))[lane];
            #pragma unroll
            for (int i = 0; i < 8; i++) {
                float4 av = *(const float4*)(aw + i * DD + k0 + kk);
                acc[i].x = fmaf(av.x, wv0.x, acc[i].x);
                acc[i].y = fmaf(av.x, wv0.y, acc[i].y);
                acc[i].z = fmaf(av.x, wv0.z, acc[i].z);
                acc[i].w = fmaf(av.x, wv0.w, acc[i].w);
                acc[i].x = fmaf(av.y, wv1.x, acc[i].x);
                acc[i].y = fmaf(av.y, wv1.y, acc[i].y);
                acc[i].z = fmaf(av.y, wv1.z, acc[i].z);
                acc[i].w = fmaf(av.y, wv1.w, acc[i].w);
                acc[i].x = fmaf(av.z, wv2.x, acc[i].x);
                acc[i].y = fmaf(av.z, wv2.y, acc[i].y);
                acc[i].z = fmaf(av.z, wv2.z, acc[i].z);
                acc[i].w = fmaf(av.z, wv2.w, acc[i].w);
                acc[i].x = fmaf(av.w, wv3.x, acc[i].x);
                acc[i].y = fmaf(av.w, wv3.y, acc[i].y);
                acc[i].z = fmaf(av.w, wv3.z, acc[i].z);
                acc[i].w = fmaf(av.w, wv3.w, acc[i].w);
            }
        }
    }

    #pragma unroll
    for (int i = 0; i < 8; i++) {
        int row = row0 + w * 8 + i;
        if (row < NN) {
            float dv = g_dinv[row];
            float4 o;
            o.x = acc[i].x * dv;
            o.y = acc[i].y * dv;
            o.z = acc[i].z * dv;
            o.w = acc[i].w * dv;
            ((float4*)(g_tmp + (size_t)row * DD))[lane] = o;
        }
    }
}

// ---------------- per-node gather accumulate ----------------------------------
// out[i] = b + dinv[i]*(tmp[i] + sum_{e in CSR[i]} tmp[src_e]) (+ res[i])
__global__ void __launch_bounds__(256) k_accum(float* __restrict__ out,
                        const float* __restrict__ b,
                        const float* __restrict__ res) {
    int node = (blockIdx.x * blockDim.x + threadIdx.x) >> 5;
    int lane = threadIdx.x & 31;
    if (node >= NN) return;

    const float4* T = (const float4*)g_tmp;
    int s0 = g_start[node];
    int cnt = g_cnt[node];

    float4 a[8];
    a[0] = T[(size_t)node * 32 + lane];   // self loop term
    #pragma unroll
    for (int j = 1; j < 8; j++) a[j] = make_float4(0.f, 0.f, 0.f, 0.f);

    int e = 0;
    for (; e + 8 <= cnt; e += 8) {
        int idx[8];
        #pragma unroll
        for (int j = 0; j < 8; j++) idx[j] = g_esrc[s0 + e + j];
        #pragma unroll
        for (int j = 0; j < 8; j++) {
            float4 v = T[(size_t)idx[j] * 32 + lane];
            a[j].x += v.x; a[j].y += v.y; a[j].z += v.z; a[j].w += v.w;
        }
    }
    for (; e < cnt; e++) {
        int i0 = g_esrc[s0 + e];
        float4 v = T[(size_t)i0 * 32 + lane];
        a[0].x += v.x; a[0].y += v.y; a[0].z += v.z; a[0].w += v.w;
    }
    #pragma unroll
    for (int j = 1; j < 8; j++) {
        a[0].x += a[j].x; a[0].y += a[j].y; a[0].z += a[j].z; a[0].w += a[j].w;
    }

    float dv = g_dinv[node];
    float4 bb = ((const float4*)b)[lane];
    float4 o;
    o.x = fmaf(dv, a[0].x, bb.x);
    o.y = fmaf(dv, a[0].y, bb.y);
    o.z = fmaf(dv, a[0].z, bb.z);
    o.w = fmaf(dv, a[0].w, bb.w);
    if (res) {
        float4 r = ((const float4*)(res))[(size_t)node * 32 + lane];
        o.x += r.x; o.y += r.y; o.z += r.z; o.w += r.w;
    }
    ((float4*)out)[(size_t)node * 32 + lane] = o;
}

// ---------------- launch ------------------------------------------------------
extern "C" void kernel_launch(void* const* d_in, const int* in_sizes, int n_in,
                              void* d_out, int out_size) {
    const float* x   = (const float*)d_in[0];
    const int*   ei  = (const int*)d_in[1];
    const int*   src = ei;
    const int*   dst = ei + EE;
    const float* lng0 = (const float*)d_in[2];
    const float* lnb0 = (const float*)d_in[3];
    const float* W0   = (const float*)d_in[4];
    const float* b0   = (const float*)d_in[5];
    const float* lng1 = (const float*)d_in[6];
    const float* lnb1 = (const float*)d_in[7];
    const float* W1   = (const float*)d_in[8];
    const float* b1   = (const float*)d_in[9];
    const float* lng2 = (const float*)d_in[10];
    const float* lnb2 = (const float*)d_in[11];
    const float* W2   = (const float*)d_in[12];
    const float* b2   = (const float*)d_in[13];
    float* out = (float*)d_out;

    float* d_x1;  cudaGetSymbolAddress((void**)&d_x1,  g_x1);
    float* d_h2;  cudaGetSymbolAddress((void**)&d_h2,  g_h2);

    // ---- CSR build + dinv (5 launches) ----
    k_zero<<<(NN + 255) / 256, 256>>>();
    k_hist<<<(EE + 255) / 256, 256>>>(dst);
    k_scan_a<<<SNB, SCH>>>();
    k_scan_c<<<SNB, SCH>>>();
    k_bucket<<<(EE + 255) / 256, 256>>>(src, dst);

    const int gemm_blocks = (NN + TR - 1) / TR;
    const int acc_blocks = (NN * 32 + 255) / 256;   // warp per node

    // layer 0: x -> g_x1 (residual = x)
    k_ln_gemm<<<gemm_blocks, 256>>>(x, lng0, lnb0, W0);
    k_accum<<<acc_blocks, 256>>>(d_x1, b0, x);

    // layer 1: g_x1 -> g_h2 (no residual)
    k_ln_gemm<<<gemm_blocks, 256>>>(d_x1, lng1, lnb1, W1);
    k_accum<<<acc_blocks, 256>>>(d_h2, b1, nullptr);

    // layer 2: g_h2 -> out (residual = g_x1)
    k_ln_gemm<<<gemm_blocks, 256>>>(d_h2, lng2, lnb2, W2);
    k_accum<<<acc_blocks, 256>>>(out, b2, d_x1);
}

// round 5
// speedup vs baseline: 1.0414x; 1.0414x over previous
#include <cuda_runtime.h>

#define NN 50000
#define DD 128
#define EE 800000
#define EPSL 1e-5f

#define SCH 512
#define SNB ((NN + SCH - 1) / SCH)   // 98

// ---------------- scratch (device globals; no allocation allowed) -------------
__device__ float g_dinv[NN];
__device__ float g_tmp[NN * DD];   // dinv[i] * (ReLU(LN(h_i)) @ W)
__device__ float g_x1[NN * DD];    // x after layer0 + residual
__device__ float g_h2[NN * DD];    // layer1 output
__device__ int   g_cnt[NN];
__device__ int   g_start[NN];
__device__ int   g_cursor[NN];
__device__ int   g_esrc[EE];       // edge srcs bucketed by dst (CSR)
__device__ int   g_csum[SNB];

// ---------------- CSR build ----------------------------------------------------
__global__ void k_zero() {
    int i = blockIdx.x * blockDim.x + threadIdx.x;
    if (i < NN) g_cnt[i] = 0;
}

__global__ void k_hist(const int* __restrict__ dst) {
    int e = blockIdx.x * blockDim.x + threadIdx.x;
    if (e < EE) atomicAdd(&g_cnt[dst[e]], 1);
}

__global__ void k_dinv() {
    int i = blockIdx.x * blockDim.x + threadIdx.x;
    if (i < NN) g_dinv[i] = rsqrtf(1.0f + (float)g_cnt[i]);
}

// per-chunk sums
__global__ void __launch_bounds__(SCH) k_scan_a() {
    __shared__ int sm[SCH];
    int t = threadIdx.x;
    int i = blockIdx.x * SCH + t;
    sm[t] = (i < NN) ? g_cnt[i] : 0;
    __syncthreads();
    for (int off = SCH / 2; off > 0; off >>= 1) {
        if (t < off) sm[t] += sm[t + off];
        __syncthreads();
    }
    if (t == 0) g_csum[blockIdx.x] = sm[0];
}

// in-chunk exclusive scan + self-computed chunk offset -> start/cursor
__global__ void __launch_bounds__(SCH) k_scan_c() {
    __shared__ int sm[SCH];
    __shared__ int base;
    int t = threadIdx.x;
    int i = blockIdx.x * SCH + t;
    int v = (i < NN) ? g_cnt[i] : 0;
    sm[t] = v;
    if (t == 0) {
        int run = 0;
        for (int j = 0; j < blockIdx.x; j++) run += g_csum[j];
        base = run;
    }
    __syncthreads();
    for (int off = 1; off < SCH; off <<= 1) {
        int x = (t >= off) ? sm[t - off] : 0;
        __syncthreads();
        sm[t] += x;
        __syncthreads();
    }
    if (i < NN) {
        int excl = sm[t] - v + base;
        g_start[i] = excl;
        g_cursor[i] = excl;
    }
}

__global__ void k_bucket(const int* __restrict__ src, const int* __restrict__ dst) {
    int e = blockIdx.x * blockDim.x + threadIdx.x;
    if (e < EE) {
        int pos = atomicAdd(&g_cursor[dst[e]], 1);
        g_esrc[pos] = src[e];
    }
}

// ---------------- fused LN + ReLU + GEMM + dinv prescale ----------------------
// g_tmp[i] = dinv[i] * ( ReLU( (h_i - mu)*rstd*g + bt ) @ W )
// Block 256 threads, tile 64 rows x 128 cols, k-tile 32. 48KB static smem.
// (R3 inner loop: scalar A broadcasts; known regs=64.)
#define TR 64
#define KT 32
__global__ void __launch_bounds__(256) k_ln_gemm(const float* __restrict__ h,
                          const float* __restrict__ g,
                          const float* __restrict__ bt,
                          const float* __restrict__ W) {
    __shared__ float As[TR * DD];    // 32KB
    __shared__ float Ws[KT * DD];    // 16KB

    int tid = threadIdx.x;
    int lane = tid & 31;
    int w = tid >> 5;
    int row0 = blockIdx.x * TR;

    // LayerNorm + ReLU into As: warp w handles rows w, w+8, ..., w+56
    for (int r = w; r < TR; r += 8) {
        int row = row0 + r;
        float4 v = make_float4(0.f, 0.f, 0.f, 0.f);
        if (row < NN) v = ((const float4*)(h + (size_t)row * DD))[lane];
        float s = v.x + v.y + v.z + v.w;
        #pragma unroll
        for (int o = 16; o; o >>= 1) s += __shfl_xor_sync(0xffffffffu, s, o);
        float mu = s * (1.0f / DD);
        float dx = v.x - mu, dy = v.y - mu, dz = v.z - mu, dw = v.w - mu;
        float q = dx * dx + dy * dy + dz * dz + dw * dw;
        #pragma unroll
        for (int o = 16; o; o >>= 1) q += __shfl_xor_sync(0xffffffffu, q, o);
        float rstd = rsqrtf(q * (1.0f / DD) + EPSL);
        float4 gg = ((const float4*)g)[lane];
        float4 bb = ((const float4*)bt)[lane];
        float4 o4;
        o4.x = fmaxf(fmaf(dx * rstd, gg.x, bb.x), 0.f);
        o4.y = fmaxf(fmaf(dy * rstd, gg.y, bb.y), 0.f);
        o4.z = fmaxf(fmaf(dz * rstd, gg.z, bb.z), 0.f);
        o4.w = fmaxf(fmaf(dw * rstd, gg.w, bb.w), 0.f);
        ((float4*)(As + r * DD))[lane] = o4;
    }

    // GEMM: warp w -> rows 8w..8w+7 ; lane -> cols 4*lane..4*lane+3
    float acc[8][4];
    #pragma unroll
    for (int i = 0; i < 8; i++)
        #pragma unroll
        for (int j = 0; j < 4; j++) acc[i][j] = 0.f;

    const float* aw = As + w * 8 * DD;

    for (int k0 = 0; k0 < DD; k0 += KT) {
        __syncthreads();
        {
            const float4* W4 = (const float4*)(W + (size_t)k0 * DD);
            float4* Ws4 = (float4*)Ws;
            #pragma unroll
            for (int i = tid; i < KT * DD / 4; i += 256) Ws4[i] = W4[i];
        }
        __syncthreads();

        #pragma unroll 8
        for (int kk = 0; kk < KT; kk++) {
            float4 wv = ((const float4*)(Ws + kk * DD))[lane];
            #pragma unroll
            for (int i = 0; i < 8; i++) {
                float va = aw[i * DD + k0 + kk];
                acc[i][0] = fmaf(va, wv.x, acc[i][0]);
                acc[i][1] = fmaf(va, wv.y, acc[i][1]);
                acc[i][2] = fmaf(va, wv.z, acc[i][2]);
                acc[i][3] = fmaf(va, wv.w, acc[i][3]);
            }
        }
    }

    #pragma unroll
    for (int i = 0; i < 8; i++) {
        int row = row0 + w * 8 + i;
        if (row < NN) {
            float dv = g_dinv[row];
            float4 o;
            o.x = acc[i][0] * dv;
            o.y = acc[i][1] * dv;
            o.z = acc[i][2] * dv;
            o.w = acc[i][3] * dv;
            ((float4*)(g_tmp + (size_t)row * DD))[lane] = o;
        }
    }
}

// ---------------- per-node gather accumulate ----------------------------------
// out[i] = b + dinv[i]*(tmp[i] + sum_{e in CSR[i]} tmp[src_e]) (+ res[i])
__global__ void __launch_bounds__(256) k_accum(float* __restrict__ out,
                        const float* __restrict__ b,
                        const float* __restrict__ res) {
    int node = (blockIdx.x * blockDim.x + threadIdx.x) >> 5;
    int lane = threadIdx.x & 31;
    if (node >= NN) return;

    const float4* T = (const float4*)g_tmp;
    int s0 = g_start[node];
    int cnt = g_cnt[node];

    float4 a[8];
    a[0] = T[(size_t)node * 32 + lane];   // self loop term
    #pragma unroll
    for (int j = 1; j < 8; j++) a[j] = make_float4(0.f, 0.f, 0.f, 0.f);

    int e = 0;
    for (; e + 8 <= cnt; e += 8) {
        int idx[8];
        #pragma unroll
        for (int j = 0; j < 8; j++) idx[j] = g_esrc[s0 + e + j];
        #pragma unroll
        for (int j = 0; j < 8; j++) {
            float4 v = T[(size_t)idx[j] * 32 + lane];
            a[j].x += v.x; a[j].y += v.y; a[j].z += v.z; a[j].w += v.w;
        }
    }
    for (; e < cnt; e++) {
        int i0 = g_esrc[s0 + e];
        float4 v = T[(size_t)i0 * 32 + lane];
        a[0].x += v.x; a[0].y += v.y; a[0].z += v.z; a[0].w += v.w;
    }
    #pragma unroll
    for (int j = 1; j < 8; j++) {
        a[0].x += a[j].x; a[0].y += a[j].y; a[0].z += a[j].z; a[0].w += a[j].w;
    }

    float dv = g_dinv[node];
    float4 bb = ((const float4*)b)[lane];
    float4 o;
    o.x = fmaf(dv, a[0].x, bb.x);
    o.y = fmaf(dv, a[0].y, bb.y);
    o.z = fmaf(dv, a[0].z, bb.z);
    o.w = fmaf(dv, a[0].w, bb.w);
    if (res) {
        float4 r = ((const float4*)(res))[(size_t)node * 32 + lane];
        o.x += r.x; o.y += r.y; o.z += r.z; o.w += r.w;
    }
    ((float4*)out)[(size_t)node * 32 + lane] = o;
}

// ---------------- launch ------------------------------------------------------
extern "C" void kernel_launch(void* const* d_in, const int* in_sizes, int n_in,
                              void* d_out, int out_size) {
    const float* x   = (const float*)d_in[0];
    const int*   ei  = (const int*)d_in[1];
    const int*   src = ei;
    const int*   dst = ei + EE;
    const float* lng0 = (const float*)d_in[2];
    const float* lnb0 = (const float*)d_in[3];
    const float* W0   = (const float*)d_in[4];
    const float* b0   = (const float*)d_in[5];
    const float* lng1 = (const float*)d_in[6];
    const float* lnb1 = (const float*)d_in[7];
    const float* W1   = (const float*)d_in[8];
    const float* b1   = (const float*)d_in[9];
    const float* lng2 = (const float*)d_in[10];
    const float* lnb2 = (const float*)d_in[11];
    const float* W2   = (const float*)d_in[12];
    const float* b2   = (const float*)d_in[13];
    float* out = (float*)d_out;

    float* d_x1;  cudaGetSymbolAddress((void**)&d_x1,  g_x1);
    float* d_h2;  cudaGetSymbolAddress((void**)&d_h2,  g_h2);

    const int gemm_blocks = (NN + TR - 1) / TR;
    const int acc_blocks = (NN * 32 + 255) / 256;   // warp per node

    // prep part 1: counts + dinv (needed by GEMM)
    k_zero<<<(NN + 255) / 256, 256>>>();
    k_hist<<<(EE + 255) / 256, 256>>>(dst);
    k_dinv<<<(NN + 255) / 256, 256>>>();

    // layer 0 GEMM hoisted here (launch #4 -> ncu profile slot)
    k_ln_gemm<<<gemm_blocks, 256>>>(x, lng0, lnb0, W0);

    // prep part 2: CSR scan + bucket (needed by accum)
    k_scan_a<<<SNB, SCH>>>();
    k_scan_c<<<SNB, SCH>>>();
    k_bucket<<<(EE + 255) / 256, 256>>>(src, dst);

    // layer 0 accum: x -> g_x1 (residual = x)
    k_accum<<<acc_blocks, 256>>>(d_x1, b0, x);

    // layer 1: g_x1 -> g_h2 (no residual)
    k_ln_gemm<<<gemm_blocks, 256>>>(d_x1, lng1, lnb1, W1);
    k_accum<<<acc_blocks, 256>>>(d_h2, b1, nullptr);

    // layer 2: g_h2 -> out (residual = g_x1)
    k_ln_gemm<<<gemm_blocks, 256>>>(d_h2, lng2, lnb2, W2);
    k_accum<<<acc_blocks, 256>>>(out, b2, d_x1);
}